// round 1
// baseline (speedup 1.0000x reference)
#include <cuda_runtime.h>

#define T_LEN 2048
#define HID   15
#define EDIM  300
#define G4    60   // 4*HID gates

// Scratch: precomputed input-projection gates for both sequences.
// [2][T_LEN][G4] floats = 983 KB (static __device__, allowed).
__device__ float g_pre[2 * T_LEN * G4];

// ---------------------------------------------------------------------------
// Kernel 1: pre[s][t][j] = b_ih[j] + b_hh[j] + sum_e emb[tok_st][e] * W_ih[j][e]
// One block per token (4096 blocks, 64 threads). Embedding row staged in smem,
// W_ih rows streamed through L1 (72 KB total, hot across blocks).
// ---------------------------------------------------------------------------
__global__ void precompute_kernel(const int* __restrict__ s1,
                                  const int* __restrict__ s2,
                                  const float* __restrict__ emb,
                                  const float* __restrict__ W_ih,
                                  const float* __restrict__ b_ih,
                                  const float* __restrict__ b_hh) {
    __shared__ float4 semb[EDIM / 4];  // 75 float4 = 300 floats

    const int bid = blockIdx.x;          // 0..4095
    const int s   = bid >> 11;           // sequence index
    const int t   = bid & (T_LEN - 1);   // timestep
    const int tok = (s == 0) ? s1[t] : s2[t];

    const float4* erow = reinterpret_cast<const float4*>(emb + (long long)tok * EDIM);
    for (int i = threadIdx.x; i < EDIM / 4; i += blockDim.x)
        semb[i] = erow[i];
    __syncthreads();

    const int j = threadIdx.x;
    if (j < G4) {
        const float4* wrow = reinterpret_cast<const float4*>(W_ih + j * EDIM);
        float a0 = 0.f, a1 = 0.f, a2 = 0.f, a3 = 0.f;
        #pragma unroll 5
        for (int e = 0; e < EDIM / 4; e++) {
            float4 wv = wrow[e];
            float4 xv = semb[e];
            a0 = fmaf(wv.x, xv.x, a0);
            a1 = fmaf(wv.y, xv.y, a1);
            a2 = fmaf(wv.z, xv.z, a2);
            a3 = fmaf(wv.w, xv.w, a3);
        }
        float acc = b_ih[j] + b_hh[j] + ((a0 + a1) + (a2 + a3));
        g_pre[(s * T_LEN + t) * G4 + j] = acc;
    }
}

// Fast activations (EX2/RCP based, ~2^-21 accuracy, no NaN for any input)
__device__ __forceinline__ float sigm(float x) {
    // 1/(1+e^-x); e^-x -> inf for very negative x, rcp(inf)=0: safe.
    return __fdividef(1.0f, 1.0f + __expf(-x));
}

// ---------------------------------------------------------------------------
// Kernel 2: both LSTM recurrences (one warp each) + fused final MLP.
// Lane mapping within a warp (per sequence):
//   lane k   (k<15): gate i_k  and gate g_k  (indices k, 30+k)
//   lane 16+k(k<15): gate f_k  and gate o_k  (indices 15+k, 45+k)
// State h_k, c_k live on lane k. h broadcast via shfl (no smem, no syncs in loop).
// ---------------------------------------------------------------------------
__global__ void recurrence_kernel(const float* __restrict__ W_hh,
                                  const float* __restrict__ W1,
                                  const float* __restrict__ b1,
                                  const float* __restrict__ W2,
                                  const float* __restrict__ b2,
                                  const float* __restrict__ h1_0,
                                  const float* __restrict__ c1_0,
                                  const float* __restrict__ h2_0,
                                  const float* __restrict__ c2_0,
                                  float* __restrict__ out) {
    const int tid  = threadIdx.x;
    const int w    = tid >> 5;   // 0: seq1, 1: seq2
    const int lane = tid & 31;

    __shared__ float sh_h[2][16];
    __shared__ float sh_hidden[25];

    const bool lowhalf = (lane < 16);
    const int  sub     = lowhalf ? lane : lane - 16;
    const bool valid   = (sub < HID);

    const int ia = valid ? (lowhalf ? sub       : 15 + sub) : 0;  // i or f
    const int ib = valid ? (lowhalf ? 30 + sub  : 45 + sub) : 0;  // g or o

    // Recurrent weight rows in registers (zero for inactive lanes)
    float Wa[HID], Wb[HID];
    #pragma unroll
    for (int kk = 0; kk < HID; kk++) {
        Wa[kk] = valid ? W_hh[ia * HID + kk] : 0.0f;
        Wb[kk] = valid ? W_hh[ib * HID + kk] : 0.0f;
    }

    // Branchless activation selection for act_b:
    //   low half  (g): tanh(x)    = 2*sigm(2x) - 1
    //   high half (o): sigmoid(x) = 1*sigm(1x) + 0
    const float sc = lowhalf ? 2.0f : 1.0f;
    const float mb = lowhalf ? 2.0f : 1.0f;
    const float cb = lowhalf ? -1.0f : 0.0f;

    const float* preA = g_pre + w * (T_LEN * G4) + ia;
    const float* preB = g_pre + w * (T_LEN * G4) + ib;

    const float* h0 = (w == 0) ? h1_0 : h2_0;
    const float* c0 = (w == 0) ? c1_0 : c2_0;
    float hval = (lowhalf && valid) ? h0[sub] : 0.0f;
    float cval = (lowhalf && valid) ? c0[sub] : 0.0f;

    // Two-deep prefetch of pre (L2-resident after kernel 1; lat ~240 cyc)
    float paC = preA[0],  pbC = preB[0];
    float paN = preA[G4], pbN = preB[G4];
    const float* pA = preA + 2 * G4;
    const float* pB = preB + 2 * G4;

    for (int t = 0; t < T_LEN; t++) {
        const float pa = paC, pb = pbC;
        paC = paN; pbC = pbN;
        if (t + 2 < T_LEN) {
            paN = __ldg(pA);
            pbN = __ldg(pB);
            pA += G4; pB += G4;
        }

        // gates = pre + W_hh . h  (h broadcast from lanes 0..14 via shfl)
        float aa = pa, ab = pb;
        #pragma unroll
        for (int kk = 0; kk < HID; kk++) {
            float hv = __shfl_sync(0xffffffffu, hval, kk);
            aa = fmaf(Wa[kk], hv, aa);
            ab = fmaf(Wb[kk], hv, ab);
        }

        // activations (no divergence: predicated constants)
        float act_a = sigm(aa);                       // i (low) / f (high)
        float act_b = fmaf(mb, sigm(sc * ab), cb);    // g (low) / o (high)

        // bring f,o to the state lanes
        float fv = __shfl_down_sync(0xffffffffu, act_a, 16);
        float ov = __shfl_down_sync(0xffffffffu, act_b, 16);

        // c' = f*c + i*g ;  h' = o * tanh(c')   (meaningful on lanes 0..14)
        float ig = act_a * act_b;
        cval = fmaf(fv, cval, ig);
        float tc = fmaf(2.0f, sigm(2.0f * cval), -1.0f);  // tanh(c')
        hval = ov * tc;
    }

    // ---- fused final MLP ----
    if (lowhalf && valid) sh_h[w][sub] = hval;
    __syncthreads();

    if (tid < 25) {
        const float* w1r = W1 + tid * (5 * HID);
        float acc = b1[tid];
        #pragma unroll
        for (int kk = 0; kk < HID; kk++) {
            float v1 = sh_h[0][kk];
            float v2 = sh_h[1][kk];
            acc = fmaf(w1r[kk],            v1,                 acc);
            acc = fmaf(w1r[HID + kk],      fabsf(v1 - v2),     acc);
            acc = fmaf(w1r[2 * HID + kk],  v2,                 acc);
            acc = fmaf(w1r[3 * HID + kk],  v1 * v2,            acc);
            acc = fmaf(w1r[4 * HID + kk],  0.5f * (v1 + v2),   acc);
        }
        sh_hidden[tid] = acc;
    }
    __syncthreads();

    if (tid < 2) {
        float acc = b2[tid];
        #pragma unroll
        for (int j = 0; j < 25; j++)
            acc = fmaf(W2[tid * 25 + j], sh_hidden[j], acc);
        out[tid] = acc;
    }
}

extern "C" void kernel_launch(void* const* d_in, const int* in_sizes, int n_in,
                              void* d_out, int out_size) {
    const int*   s1   = (const int*)  d_in[0];
    const int*   s2   = (const int*)  d_in[1];
    const float* emb  = (const float*)d_in[2];
    const float* W_ih = (const float*)d_in[3];
    const float* W_hh = (const float*)d_in[4];
    const float* b_ih = (const float*)d_in[5];
    const float* b_hh = (const float*)d_in[6];
    const float* W1   = (const float*)d_in[7];
    const float* b1   = (const float*)d_in[8];
    const float* W2   = (const float*)d_in[9];
    const float* b2   = (const float*)d_in[10];
    const float* h1_0 = (const float*)d_in[11];
    const float* c1_0 = (const float*)d_in[12];
    const float* h2_0 = (const float*)d_in[13];
    const float* c2_0 = (const float*)d_in[14];
    float* out = (float*)d_out;

    precompute_kernel<<<2 * T_LEN, 64>>>(s1, s2, emb, W_ih, b_ih, b_hh);
    recurrence_kernel<<<1, 64>>>(W_hh, W1, b1, W2, b2,
                                 h1_0, c1_0, h2_0, c2_0, out);
}

// round 2
// speedup vs baseline: 2.7695x; 2.7695x over previous
#include <cuda_runtime.h>

#define T_LEN 2048
#define HID   15
#define EDIM  300
#define G4    60            // 4*HID gates
#define TPAD  (T_LEN + 4)   // pad so prefetch never needs a branch

// Precomputed input-projection gates, padded: [2][TPAD][G4]
__device__ float g_pre[2 * TPAD * G4];

// ---------------------------------------------------------------------------
// Kernel 1: pre[s][t][j] = b_ih[j] + b_hh[j] + emb[tok]·W_ih[j]
// ---------------------------------------------------------------------------
__global__ void precompute_kernel(const int* __restrict__ s1,
                                  const int* __restrict__ s2,
                                  const float* __restrict__ emb,
                                  const float* __restrict__ W_ih,
                                  const float* __restrict__ b_ih,
                                  const float* __restrict__ b_hh) {
    __shared__ float4 semb[EDIM / 4];

    const int bid = blockIdx.x;
    const int s   = bid >> 11;
    const int t   = bid & (T_LEN - 1);
    const int tok = (s == 0) ? s1[t] : s2[t];

    const float4* erow = reinterpret_cast<const float4*>(emb + (long long)tok * EDIM);
    for (int i = threadIdx.x; i < EDIM / 4; i += blockDim.x)
        semb[i] = erow[i];
    __syncthreads();

    const int j = threadIdx.x;
    if (j < G4) {
        const float4* wrow = reinterpret_cast<const float4*>(W_ih + j * EDIM);
        float a0 = 0.f, a1 = 0.f, a2 = 0.f, a3 = 0.f;
        #pragma unroll 5
        for (int e = 0; e < EDIM / 4; e++) {
            float4 wv = wrow[e];
            float4 xv = semb[e];
            a0 = fmaf(wv.x, xv.x, a0);
            a1 = fmaf(wv.y, xv.y, a1);
            a2 = fmaf(wv.z, xv.z, a2);
            a3 = fmaf(wv.w, xv.w, a3);
        }
        g_pre[(s * TPAD + t) * G4 + j] = b_ih[j] + b_hh[j] + ((a0 + a1) + (a2 + a3));
    }
}

// Single-MUFU primitives (guaranteed 1 instr each)
__device__ __forceinline__ float ex2f(float x) {
    float y; asm("ex2.approx.f32 %0, %1;" : "=f"(y) : "f"(x)); return y;
}
__device__ __forceinline__ float rcpf(float x) {
    float y; asm("rcp.approx.f32 %0, %1;" : "=f"(y) : "f"(x)); return y;
}
// sigmoid(s*x) where k = -s*log2(e):  rcp(1 + 2^(k*x))
__device__ __forceinline__ float sig_k(float x, float k) {
    return rcpf(1.0f + ex2f(k * x));
}

// ---------------------------------------------------------------------------
// Kernel 2: both LSTM recurrences (1 warp each) + fused MLP.
// Lane k<15:  gates i_k (row k),    g_k (row 30+k); holds state h_k, c_k.
// Lane 16+k:  gates f_k (row 15+k), o_k (row 45+k).
// h broadcast via smem (1 STS + 4 LDS.128), no per-step branches.
// ---------------------------------------------------------------------------
__global__ __launch_bounds__(64, 1)
void recurrence_kernel(const float* __restrict__ W_hh,
                       const float* __restrict__ W1,
                       const float* __restrict__ b1,
                       const float* __restrict__ W2,
                       const float* __restrict__ b2,
                       const float* __restrict__ h1_0,
                       const float* __restrict__ c1_0,
                       const float* __restrict__ h2_0,
                       const float* __restrict__ c2_0,
                       float* __restrict__ out) {
    const int tid  = threadIdx.x;
    const int w    = tid >> 5;
    const int lane = tid & 31;

    __shared__ __align__(16) float sh_h[2][16];
    __shared__ float sh_hidden[25];

    const bool lowhalf = (lane < 16);
    const int  sub     = lowhalf ? lane : lane - 16;
    const bool valid   = (sub < HID);

    const int ia = valid ? (lowhalf ? sub      : 15 + sub) : 0;  // i / f
    const int ib = valid ? (lowhalf ? 30 + sub : 45 + sub) : 0;  // g / o

    // Recurrent weight rows in registers (padded to 16, entry 15 = 0)
    float Wa[16], Wb[16];
    #pragma unroll
    for (int m = 0; m < HID; m++) {
        Wa[m] = valid ? W_hh[ia * HID + m] : 0.0f;
        Wb[m] = valid ? W_hh[ib * HID + m] : 0.0f;
    }
    Wa[15] = 0.0f; Wb[15] = 0.0f;

    // act_b:  low (g): tanh(x) = 2*sig(2x) - 1    high (o): sigmoid(x)
    const float kb = lowhalf ? -2.885390082f : -1.442695041f; // -s*log2e
    const float mb = lowhalf ? 2.0f : 1.0f;
    const float cb = lowhalf ? -1.0f : 0.0f;

    const float* baseA = g_pre + w * (TPAD * G4) + ia;
    const float* baseB = g_pre + w * (TPAD * G4) + ib;

    const float* h0 = (w == 0) ? h1_0 : h2_0;
    const float* c0 = (w == 0) ? c1_0 : c2_0;
    float cval = (lowhalf && valid) ? c0[sub] : 0.0f;

    // init smem h (pad slot 15 = 0)
    if (lowhalf) sh_h[w][lane] = (valid ? h0[lane] : 0.0f);
    __syncthreads();

    // two-deep register prefetch of pre (always-on; pad absorbs overrun)
    float paC = baseA[0],      pbC = baseB[0];
    float paN = baseA[G4],     pbN = baseB[G4];
    int   off = 2 * G4;

    const float4* s4 = reinterpret_cast<const float4*>(sh_h[w]);

    #pragma unroll 2
    for (int t = 0; t < T_LEN; t++) {
        const float pa = paC, pb = pbC;
        paC = paN; pbC = pbN;
        paN = __ldg(baseA + off);
        pbN = __ldg(baseB + off);
        off += G4;

        // h broadcast: 4x LDS.128 (all lanes same address -> broadcast)
        float4 h0v = s4[0], h1v = s4[1], h2v = s4[2], h3v = s4[3];

        // 4-way split dot products (depth 4 + tree 2)
        float a0 = fmaf(Wa[0], h0v.x, pa);
        a0 = fmaf(Wa[1], h0v.y, a0); a0 = fmaf(Wa[2], h0v.z, a0); a0 = fmaf(Wa[3], h0v.w, a0);
        float a1 = Wa[4] * h1v.x;
        a1 = fmaf(Wa[5], h1v.y, a1); a1 = fmaf(Wa[6], h1v.z, a1); a1 = fmaf(Wa[7], h1v.w, a1);
        float a2 = Wa[8] * h2v.x;
        a2 = fmaf(Wa[9], h2v.y, a2); a2 = fmaf(Wa[10], h2v.z, a2); a2 = fmaf(Wa[11], h2v.w, a2);
        float a3 = Wa[12] * h3v.x;
        a3 = fmaf(Wa[13], h3v.y, a3); a3 = fmaf(Wa[14], h3v.z, a3);
        float aa = (a0 + a1) + (a2 + a3);

        float e0 = fmaf(Wb[0], h0v.x, pb);
        e0 = fmaf(Wb[1], h0v.y, e0); e0 = fmaf(Wb[2], h0v.z, e0); e0 = fmaf(Wb[3], h0v.w, e0);
        float e1 = Wb[4] * h1v.x;
        e1 = fmaf(Wb[5], h1v.y, e1); e1 = fmaf(Wb[6], h1v.z, e1); e1 = fmaf(Wb[7], h1v.w, e1);
        float e2 = Wb[8] * h2v.x;
        e2 = fmaf(Wb[9], h2v.y, e2); e2 = fmaf(Wb[10], h2v.z, e2); e2 = fmaf(Wb[11], h2v.w, e2);
        float e3 = Wb[12] * h3v.x;
        e3 = fmaf(Wb[13], h3v.y, e3); e3 = fmaf(Wb[14], h3v.z, e3);
        float ab = (e0 + e1) + (e2 + e3);

        // activations: i/f sigmoid; g tanh (via scaled sigmoid) / o sigmoid
        float act_a = sig_k(aa, -1.442695041f);
        float act_b = fmaf(mb, sig_k(ab, kb), cb);

        // bring f,o to the state lanes
        float fv = __shfl_down_sync(0xffffffffu, act_a, 16);
        float ov = __shfl_down_sync(0xffffffffu, act_b, 16);

        float ig = act_a * act_b;
        cval = fmaf(fv, cval, ig);
        float tc = fmaf(2.0f, sig_k(cval, -2.885390082f), -1.0f);  // tanh(c)
        float hval = ov * tc;

        if (lane < HID) sh_h[w][lane] = hval;   // STS (pad slot untouched)
        __syncwarp();
    }

    __syncthreads();

    // ---- fused final MLP ----
    if (tid < 25) {
        const float* w1r = W1 + tid * (5 * HID);
        float acc = b1[tid];
        #pragma unroll
        for (int kk = 0; kk < HID; kk++) {
            float v1 = sh_h[0][kk];
            float v2 = sh_h[1][kk];
            acc = fmaf(w1r[kk],           v1,               acc);
            acc = fmaf(w1r[HID + kk],     fabsf(v1 - v2),   acc);
            acc = fmaf(w1r[2 * HID + kk], v2,               acc);
            acc = fmaf(w1r[3 * HID + kk], v1 * v2,          acc);
            acc = fmaf(w1r[4 * HID + kk], 0.5f * (v1 + v2), acc);
        }
        sh_hidden[tid] = acc;
    }
    __syncthreads();

    if (tid < 2) {
        float acc = b2[tid];
        #pragma unroll
        for (int j = 0; j < 25; j++)
            acc = fmaf(W2[tid * 25 + j], sh_hidden[j], acc);
        out[tid] = acc;
    }
}

extern "C" void kernel_launch(void* const* d_in, const int* in_sizes, int n_in,
                              void* d_out, int out_size) {
    const int*   s1   = (const int*)  d_in[0];
    const int*   s2   = (const int*)  d_in[1];
    const float* emb  = (const float*)d_in[2];
    const float* W_ih = (const float*)d_in[3];
    const float* W_hh = (const float*)d_in[4];
    const float* b_ih = (const float*)d_in[5];
    const float* b_hh = (const float*)d_in[6];
    const float* W1   = (const float*)d_in[7];
    const float* b1   = (const float*)d_in[8];
    const float* W2   = (const float*)d_in[9];
    const float* b2   = (const float*)d_in[10];
    const float* h1_0 = (const float*)d_in[11];
    const float* c1_0 = (const float*)d_in[12];
    const float* h2_0 = (const float*)d_in[13];
    const float* c2_0 = (const float*)d_in[14];
    float* out = (float*)d_out;

    precompute_kernel<<<2 * T_LEN, 64>>>(s1, s2, emb, W_ih, b_ih, b_hh);
    recurrence_kernel<<<1, 64>>>(W_hh, W1, b1, W2, b2,
                                 h1_0, c1_0, h2_0, c2_0, out);
}

// round 4
// speedup vs baseline: 3.1777x; 1.1474x over previous
#include <cuda_runtime.h>

#define T_LEN 2048
#define HID   15
#define EDIM  300
#define G4    60            // 4*HID gates
#define TPAD  (T_LEN + 4)   // pad so prefetch never needs a branch

// Precomputed input-projection gates, padded: [2][TPAD][G4]
__device__ float g_pre[2 * TPAD * G4];

// ---------------------------------------------------------------------------
// Kernel 1: pre[s][t][j] = b_ih[j] + b_hh[j] + emb[tok]·W_ih[j]
// ---------------------------------------------------------------------------
__global__ void precompute_kernel(const int* __restrict__ s1,
                                  const int* __restrict__ s2,
                                  const float* __restrict__ emb,
                                  const float* __restrict__ W_ih,
                                  const float* __restrict__ b_ih,
                                  const float* __restrict__ b_hh) {
    __shared__ float4 semb[EDIM / 4];

    const int bid = blockIdx.x;
    const int s   = bid >> 11;
    const int t   = bid & (T_LEN - 1);
    const int tok = (s == 0) ? s1[t] : s2[t];

    const float4* erow = reinterpret_cast<const float4*>(emb + (long long)tok * EDIM);
    for (int i = threadIdx.x; i < EDIM / 4; i += blockDim.x)
        semb[i] = erow[i];
    __syncthreads();

    const int j = threadIdx.x;
    if (j < G4) {
        const float4* wrow = reinterpret_cast<const float4*>(W_ih + j * EDIM);
        float a0 = 0.f, a1 = 0.f, a2 = 0.f, a3 = 0.f;
        #pragma unroll 5
        for (int e = 0; e < EDIM / 4; e++) {
            float4 wv = wrow[e];
            float4 xv = semb[e];
            a0 = fmaf(wv.x, xv.x, a0);
            a1 = fmaf(wv.y, xv.y, a1);
            a2 = fmaf(wv.z, xv.z, a2);
            a3 = fmaf(wv.w, xv.w, a3);
        }
        g_pre[(s * TPAD + t) * G4 + j] = b_ih[j] + b_hh[j] + ((a0 + a1) + (a2 + a3));
    }
}

// Hardware tanh (sm_75+): single MUFU.TANH, lat ~16 cyc
__device__ __forceinline__ float tanhfast(float x) {
    float y; asm("tanh.approx.f32 %0, %1;" : "=f"(y) : "f"(x)); return y;
}
// sigmoid(x) = 0.5*tanh(0.5x) + 0.5   (FMUL + MUFU + FFMA = ~24 cyc)
__device__ __forceinline__ float sigfast(float x) {
    return fmaf(0.5f, tanhfast(0.5f * x), 0.5f);
}

// ---------------------------------------------------------------------------
// Kernel 2: both LSTM recurrences (1 warp each) + fused MLP.
// Lane k<15:  gates i_k (row k),    g_k (row 30+k); holds state h_k, c_k.
// Lane 16+k:  gates f_k (row 15+k), o_k (row 45+k).
// h broadcast via 15 pipelined SHFL.IDX (no smem, no barriers in loop).
// ---------------------------------------------------------------------------
__global__ __launch_bounds__(64, 1)
void recurrence_kernel(const float* __restrict__ W_hh,
                       const float* __restrict__ W1,
                       const float* __restrict__ b1,
                       const float* __restrict__ W2,
                       const float* __restrict__ b2,
                       const float* __restrict__ h1_0,
                       const float* __restrict__ c1_0,
                       const float* __restrict__ h2_0,
                       const float* __restrict__ c2_0,
                       float* __restrict__ out) {
    const int tid  = threadIdx.x;
    const int w    = tid >> 5;
    const int lane = tid & 31;

    __shared__ float sh_h[2][16];
    __shared__ float sh_hidden[25];

    const bool lowhalf = (lane < 16);
    const int  sub     = lowhalf ? lane : lane - 16;
    const bool valid   = (sub < HID);

    const int ia = valid ? (lowhalf ? sub      : 15 + sub) : 0;  // i / f
    const int ib = valid ? (lowhalf ? 30 + sub : 45 + sub) : 0;  // g / o

    // Recurrent weight rows in registers
    float Wa[HID], Wb[HID];
    #pragma unroll
    for (int m = 0; m < HID; m++) {
        Wa[m] = valid ? W_hh[ia * HID + m] : 0.0f;
        Wb[m] = valid ? W_hh[ib * HID + m] : 0.0f;
    }

    // act_b:  low (g): tanh(ab) -> sc=1,  mb=1,   cb=0
    //         high(o): sigm(ab) -> sc=.5, mb=.5,  cb=.5
    const float sc = lowhalf ? 1.0f : 0.5f;
    const float mb = lowhalf ? 1.0f : 0.5f;
    const float cb = lowhalf ? 0.0f : 0.5f;

    const float* baseA = g_pre + w * (TPAD * G4) + ia;
    const float* baseB = g_pre + w * (TPAD * G4) + ib;

    const float* h0 = (w == 0) ? h1_0 : h2_0;
    const float* c0 = (w == 0) ? c1_0 : c2_0;
    float cval = (lowhalf && valid) ? c0[sub] : 0.0f;
    float hval = (lowhalf && valid) ? h0[sub] : 0.0f;  // lane k holds h_k

    // two-deep register prefetch of pre (pad absorbs overrun)
    float paC = baseA[0],  pbC = baseB[0];
    float paN = baseA[G4], pbN = baseB[G4];
    int   off = 2 * G4;

    #pragma unroll 2
    for (int t = 0; t < T_LEN; t++) {
        const float pa = paC, pb = pbC;
        paC = paN; pbC = pbN;
        paN = __ldg(baseA + off);
        pbN = __ldg(baseB + off);
        off += G4;

        // broadcast h_0..h_14 (15 independent SHFL.IDX, pipelined)
        float h0v  = __shfl_sync(0xffffffffu, hval, 0);
        float h1v  = __shfl_sync(0xffffffffu, hval, 1);
        float h2v  = __shfl_sync(0xffffffffu, hval, 2);
        float h3v  = __shfl_sync(0xffffffffu, hval, 3);
        float h4v  = __shfl_sync(0xffffffffu, hval, 4);
        float h5v  = __shfl_sync(0xffffffffu, hval, 5);
        float h6v  = __shfl_sync(0xffffffffu, hval, 6);
        float h7v  = __shfl_sync(0xffffffffu, hval, 7);
        float h8v  = __shfl_sync(0xffffffffu, hval, 8);
        float h9v  = __shfl_sync(0xffffffffu, hval, 9);
        float h10v = __shfl_sync(0xffffffffu, hval, 10);
        float h11v = __shfl_sync(0xffffffffu, hval, 11);
        float h12v = __shfl_sync(0xffffffffu, hval, 12);
        float h13v = __shfl_sync(0xffffffffu, hval, 13);
        float h14v = __shfl_sync(0xffffffffu, hval, 14);

        // 4-way split dot products, consume shfl results in arrival order
        float a0 = fmaf(Wa[0], h0v, pa);
        float e0 = fmaf(Wb[0], h0v, pb);
        a0 = fmaf(Wa[1], h1v, a0);  e0 = fmaf(Wb[1], h1v, e0);
        float a1 = Wa[2] * h2v;     float e1 = Wb[2] * h2v;
        a1 = fmaf(Wa[3], h3v, a1);  e1 = fmaf(Wb[3], h3v, e1);
        float a2 = Wa[4] * h4v;     float e2 = Wb[4] * h4v;
        a2 = fmaf(Wa[5], h5v, a2);  e2 = fmaf(Wb[5], h5v, e2);
        float a3 = Wa[6] * h6v;     float e3 = Wb[6] * h6v;
        a3 = fmaf(Wa[7], h7v, a3);  e3 = fmaf(Wb[7], h7v, e3);
        a0 = fmaf(Wa[8], h8v, a0);  e0 = fmaf(Wb[8], h8v, e0);
        a1 = fmaf(Wa[9], h9v, a1);  e1 = fmaf(Wb[9], h9v, e1);
        a2 = fmaf(Wa[10], h10v, a2); e2 = fmaf(Wb[10], h10v, e2);
        a3 = fmaf(Wa[11], h11v, a3); e3 = fmaf(Wb[11], h11v, e3);
        a0 = fmaf(Wa[12], h12v, a0); e0 = fmaf(Wb[12], h12v, e0);
        a1 = fmaf(Wa[13], h13v, a1); e1 = fmaf(Wb[13], h13v, e1);
        a2 = fmaf(Wa[14], h14v, a2); e2 = fmaf(Wb[14], h14v, e2);
        float aa = (a0 + a1) + (a2 + a3);
        float ab = (e0 + e1) + (e2 + e3);

        // activations: act_a = sigmoid (i low / f high);
        //              act_b = tanh (g low) / sigmoid (o high), branchless
        float act_a = sigfast(aa);
        float act_b = fmaf(mb, tanhfast(sc * ab), cb);

        // bring f,o to the state lanes
        float fv = __shfl_down_sync(0xffffffffu, act_a, 16);
        float ov = __shfl_down_sync(0xffffffffu, act_b, 16);

        float ig = act_a * act_b;              // i*g (valid on low lanes)
        cval = fmaf(fv, cval, ig);             // c' = f*c + i*g
        hval = ov * tanhfast(cval);            // h' = o * tanh(c')
    }

    // ---- fused final MLP ----
    if (lowhalf && valid) sh_h[w][sub] = hval;
    __syncthreads();

    if (tid < 25) {
        const float* w1r = W1 + tid * (5 * HID);
        float acc = b1[tid];
        #pragma unroll
        for (int kk = 0; kk < HID; kk++) {
            float v1 = sh_h[0][kk];
            float v2 = sh_h[1][kk];
            acc = fmaf(w1r[kk],           v1,               acc);
            acc = fmaf(w1r[HID + kk],     fabsf(v1 - v2),   acc);
            acc = fmaf(w1r[2 * HID + kk], v2,               acc);
            acc = fmaf(w1r[3 * HID + kk], v1 * v2,          acc);
            acc = fmaf(w1r[4 * HID + kk], 0.5f * (v1 + v2), acc);
        }
        sh_hidden[tid] = acc;
    }
    __syncthreads();

    if (tid < 2) {
        float acc = b2[tid];
        #pragma unroll
        for (int j = 0; j < 25; j++)
            acc = fmaf(W2[tid * 25 + j], sh_hidden[j], acc);
        out[tid] = acc;
    }
}

extern "C" void kernel_launch(void* const* d_in, const int* in_sizes, int n_in,
                              void* d_out, int out_size) {
    const int*   s1   = (const int*)  d_in[0];
    const int*   s2   = (const int*)  d_in[1];
    const float* emb  = (const float*)d_in[2];
    const float* W_ih = (const float*)d_in[3];
    const float* W_hh = (const float*)d_in[4];
    const float* b_ih = (const float*)d_in[5];
    const float* b_hh = (const float*)d_in[6];
    const float* W1   = (const float*)d_in[7];
    const float* b1   = (const float*)d_in[8];
    const float* W2   = (const float*)d_in[9];
    const float* b2   = (const float*)d_in[10];
    const float* h1_0 = (const float*)d_in[11];
    const float* c1_0 = (const float*)d_in[12];
    const float* h2_0 = (const float*)d_in[13];
    const float* c2_0 = (const float*)d_in[14];
    float* out = (float*)d_out;

    precompute_kernel<<<2 * T_LEN, 64>>>(s1, s2, emb, W_ih, b_ih, b_hh);
    recurrence_kernel<<<1, 64>>>(W_hh, W1, b1, W2, b2,
                                 h1_0, c1_0, h2_0, c2_0, out);
}